// round 17
// baseline (speedup 1.0000x reference)
#include <cuda_runtime.h>
#include <math.h>

// ACT_R activation recurrence — wavefront column sweep (R7 champion skeleton)
// + co-resident-CTA phase stagger.
// sp: [S=512, B=256, 1] f32 (sorted along S).  w: [a, c, s, tau, h].
// out: [S-1, B, 1] f32.
//
//   E_i = sum_{j<i} max(sc_i - sc_j, 1)^{p_j},  p_j = -(c*E_j + a),  E_0 = 0
//   out[i-1] = sigmoid((log(E_i) - tau)/s)
//
// One block per batch element (grid=256), one thread per row (block=512),
// natural warp order. p_j published via NaN-sentinel smem; group-of-4 poll
// with nanosleep; FFMA-shortened shfl diagonal chain.
//
// Stagger: with occ=2 the classic launch co-schedules bid and bid+148 on one
// SM with synchronized phases; their combined consumer MUFU demand
// (~56 cyc/col) exceeds the chain production rate (~50 cyc/col), so the MUFU
// queue builds and both serial chains pay a persistent queue toll
// (137 cyc/step measured vs ~55 solo). Parking the second CTA ~15K cycles
// de-synchronizes the phases: B's chain-heavy/low-MUFU start overlaps A's
// consumer-heavy tail instead of colliding with A's chain phase.

#define S_LEN 512
#define BATCH 256
#define STAGGER_CYC 15000ll

__device__ __forceinline__ float ex2f(float x) {
    float y; asm("ex2.approx.ftz.f32 %0, %1;" : "=f"(y) : "f"(x)); return y;
}
__device__ __forceinline__ float lg2f(float x) {
    float y; asm("lg2.approx.ftz.f32 %0, %1;" : "=f"(y) : "f"(x)); return y;
}
__device__ __forceinline__ float4 lds_v4_vol(const float* p) {
    float4 v; unsigned a = (unsigned)__cvta_generic_to_shared(p);
    asm volatile("ld.volatile.shared.v4.f32 {%0,%1,%2,%3}, [%4];"
                 : "=f"(v.x), "=f"(v.y), "=f"(v.z), "=f"(v.w) : "r"(a));
    return v;
}

__global__ void __launch_bounds__(S_LEN, 2)
actr_kernel(const float* __restrict__ sp, const float* __restrict__ w,
            float* __restrict__ out) {
    __shared__ __align__(16) float sc[S_LEN];   // scaled timestamps
    __shared__ __align__(16) float psm[S_LEN];  // published p_j (NaN = not ready)

    const int b    = blockIdx.x;
    const int t    = threadIdx.x;          // owned row (natural order)
    const int lane = t & 31;
    const int base = t & ~31;              // this warp's diagonal base row

    // ---- phase stagger: park the second CTA of each co-resident pair ----
    if (b >= 148) {
        long long t0 = clock64();
        while (clock64() - t0 < STAGGER_CYC) __nanosleep(256);
    }

    const float a = w[0], c = w[1], s = w[2], tau = w[3], h = w[4];
    const float scale = 86400.0f * h;

    const float my_sc = sp[t * BATCH + b] * scale;
    sc[t]  = my_sc;
    psm[t] = __int_as_float(0x7fc00000);   // NaN sentinel
    __syncthreads();

    volatile float* vp = psm;
    float accA = 0.f, accB = 0.f;          // dual accumulators for FADD ILP

    // ---- off-diagonal columns j = 0 .. base-1, groups of 4 ----
    for (int j = 0; j < base; j += 4) {
        // lg2s depend only on timestamps: issue BEFORE the poll to fill waits
        const float4 s4 = *reinterpret_cast<const float4*>(&sc[j]);
        float l0 = lg2f(fmaxf(my_sc - s4.x, 1.f));
        float l1 = lg2f(fmaxf(my_sc - s4.y, 1.f));
        float l2 = lg2f(fmaxf(my_sc - s4.z, 1.f));
        float l3 = lg2f(fmaxf(my_sc - s4.w, 1.f));
        // publishes are strictly in column order: once j+3 is ready, all are
        float p3 = vp[j + 3];
        while (__isnanf(p3)) { __nanosleep(40); p3 = vp[j + 3]; }
        asm volatile("" ::: "memory");     // keep group read below the poll
        float4 p4 = lds_v4_vol(&psm[j]);
        accA += ex2f(p4.x * l0);  accB += ex2f(p4.y * l1);
        accA += ex2f(p4.z * l2);  accB += ex2f(p4.w * l3);
    }
    float acc = accA + accB;

    // ---- diagonal block: serial chain via shfl (FFMA-shortened step) ----
    // q = -(c*acc + a) over columns accumulated so far (off-chain).
    // Lane k+1's publish value: p = q_prev + (-c)*term_k (one FFMA on chain).
    const float negc = -c;
    float q = -fmaf(c, acc, a);            // valid p for lane 0 (cols < base)
    float p_mine = q;
    #pragma unroll 1
    for (int k = 0; k < 31; ++k) {
        float l = lg2f(fmaxf(my_sc - sc[base + k], 1.f));  // off-chain
        if (lane == k) vp[base + k] = p_mine;  // publish for successor warps
        float pj = __shfl_sync(0xffffffffu, p_mine, k);
        float term = ex2f(pj * l);             // latency-critical: MUFU
        if (lane == k + 1) p_mine = fmaf(negc, term, q);   // fast-path publish
        if (lane > k) {
            acc += term;                   // off-chain bookkeeping
            q = -fmaf(c, acc, a);          // q for this lane's later fast-path
        }
    }
    if (lane == 31) vp[base + 31] = p_mine;   // last column for successor warps

    // ---- epilogue: sigmoid((m - tau)/s), m = log(E) ----
    if (t >= 1) {
        const float LN2 = 0.69314718055994530942f;
        const float inv_sln2 = 1.0f / (s * LN2);
        float m = lg2f(acc) * LN2;
        float e = ex2f((tau - m) * inv_sln2);
        out[(t - 1) * BATCH + b] = __fdividef(1.f, 1.f + e);
    }
}

extern "C" void kernel_launch(void* const* d_in, const int* in_sizes, int n_in,
                              void* d_out, int out_size) {
    const float* sp = (const float*)d_in[0];
    const float* w  = (const float*)d_in[1];
    float* out      = (float*)d_out;
    (void)in_sizes; (void)n_in; (void)out_size;
    actr_kernel<<<BATCH, S_LEN>>>(sp, w, out);
}